// round 3
// baseline (speedup 1.0000x reference)
#include <cuda_runtime.h>
#include <cstdint>

// Problem shape (fixed by reference):
//   x:       [64, 1, 512, 512] f32
//   kernels: [5, 1, 3, 3]      f32
//   biases:  [5]               f32
//   conv VALID -> [64,5,510,510]; +bias; maxpool2x2 -> [64,5,255,255]; relu.

#define TX 32
#define TY 8
#define IW (2 * TX + 2)    // 66 floats per tile row
#define IW2 (IW / 2)       // 33 float2 per tile row
#define IH (2 * TY + 2)    // 18
#define INW 512
#define POW 255            // pooled output width/height

__global__ __launch_bounds__(TX * TY)
void fused_conv_bias_pool_relu(const float* __restrict__ x,
                               const float* __restrict__ w,
                               const float* __restrict__ b,
                               float* __restrict__ out)
{
    __shared__ float sIn[IH][IW];
    __shared__ float sW[5][9];
    __shared__ float sB[5];

    const int n   = blockIdx.z;
    const int pw0 = blockIdx.x * TX;
    const int ph0 = blockIdx.y * TY;
    const int tid = threadIdx.y * TX + threadIdx.x;

    // Stage weights + biases into shared (50 floats).
    if (tid < 45) sW[tid / 9][tid % 9] = w[tid];
    else if (tid < 50) sB[tid - 45] = b[tid - 45];

    // Cooperative float2-vectorized load of the 66x18 input tile.
    // ix0 is even and rows are 512 floats, so every in-range float2 is
    // 8B-aligned. Out-of-range -> 0 (never consumed by in-range outputs).
    const float* __restrict__ xn = x + (size_t)n * INW * INW;
    const int ix0 = 2 * pw0;        // even
    const int iy0 = 2 * ph0;
    #pragma unroll
    for (int i = tid; i < IH * IW2; i += TX * TY) {
        const int r  = i / IW2;
        const int c2 = i - r * IW2;           // float2 index within row
        const int gy = iy0 + r;
        const int gx = ix0 + 2 * c2;
        float2 v;
        if (gy < INW && gx + 1 < INW) {
            v = *reinterpret_cast<const float2*>(xn + (size_t)gy * INW + gx);
        } else {
            v.x = (gy < INW && gx < INW) ? xn[(size_t)gy * INW + gx] : 0.0f;
            v.y = 0.0f;
        }
        sIn[r][2 * c2]     = v.x;
        sIn[r][2 * c2 + 1] = v.y;
    }
    __syncthreads();

    const int pw = pw0 + threadIdx.x;
    const int ph = ph0 + threadIdx.y;
    if (pw >= POW || ph >= POW) return;   // no further barriers below

    // Pull this thread's 4x4 input patch into registers once.
    // Row base index 2*tx is even and sIn rows are 8B-aligned (IW=66 even),
    // so float2 reads are legal; LDS.64 of contiguous lanes is conflict-free.
    float p[4][4];
    #pragma unroll
    for (int r = 0; r < 4; r++) {
        const float2* row = reinterpret_cast<const float2*>(
            &sIn[2 * threadIdx.y + r][2 * threadIdx.x]);
        float2 a = row[0];
        float2 c = row[1];
        p[r][0] = a.x; p[r][1] = a.y; p[r][2] = c.x; p[r][3] = c.y;
    }

    const size_t obase = (((size_t)n * 5) * POW + ph) * POW + pw;
    const size_t cstride = (size_t)POW * POW;

    #pragma unroll
    for (int ch = 0; ch < 5; ch++) {
        float k[9];
        #pragma unroll
        for (int i = 0; i < 9; i++) k[i] = sW[ch][i];
        const float bias = sB[ch];

        float m = -3.4e38f;
        #pragma unroll
        for (int dy = 0; dy < 2; dy++) {
            #pragma unroll
            for (int dx = 0; dx < 2; dx++) {
                float acc = bias;
                #pragma unroll
                for (int ky = 0; ky < 3; ky++)
                    #pragma unroll
                    for (int kx = 0; kx < 3; kx++)
                        acc = fmaf(p[dy + ky][dx + kx], k[ky * 3 + kx], acc);
                m = fmaxf(m, acc);
            }
        }
        out[obase + (size_t)ch * cstride] = fmaxf(m, 0.0f);
    }
}

extern "C" void kernel_launch(void* const* d_in, const int* in_sizes, int n_in,
                              void* d_out, int out_size)
{
    const float* x = (const float*)d_in[0];
    const float* w = (const float*)d_in[1];
    const float* b = (const float*)d_in[2];
    float* out = (float*)d_out;

    dim3 block(TX, TY, 1);                       // 256 threads
    dim3 grid((POW + TX - 1) / TX,               // 8
              (POW + TY - 1) / TY,               // 32
              64);                               // batch
    fused_conv_bias_pool_relu<<<grid, block>>>(x, w, b, out);
}